// round 9
// baseline (speedup 1.0000x reference)
#include <cuda_runtime.h>
#include <cstdint>

// ---------------------------------------------------------------------------
// PCQLinear via exact integer algebra:
//   w_q = s*(q-z), q in [0,255]  ->  B8 = q-128 in [-128,127] (exact s8)
//   x   ~= xi/4096, xi = d1*256 + d0  (d1 s8, d0 u8), |xi| <= 32768
//   out = (s/4096)*(xi @ B8^T) + s*(128-z)*rowsum(xi)/4096 + bias
// GEMM: 2x mma.sync m16n8k32 (s8.s8 + u8.s8), s32 accum (bit-exact),
// double-precision combine in epilogue. Then per-cluster min/max -> EMA ->
// fakequant as before.
// ---------------------------------------------------------------------------

#define FLT_BIG 3.402823466e38f
#define XSC 4096.0f

#define BM 128
#define BN 128
#define NTH 256
#define STG_B 24576            // d1 8K | d0 8K | B8 8K  (128 rows x 64B each)
#define OFF_D0 8192
#define OFF_B  16384
#define NSTG 4
#define SMEM_BYTES (NSTG * STG_B)   // 96 KB

// Scratch (allocation-free: __device__ globals)
__device__ signed char g_b8[4096l * 4096];      // q - 128 (exact s8)
__device__ unsigned char g_d1[10240l * 4096];   // hi digit (s8 bit pattern)
__device__ unsigned char g_d0[10240l * 4096];   // lo digit (u8)
__device__ float g_rs[10240];                   // per-row sum of xi (as float)
__device__ unsigned g_wmin_u, g_wmax_u;
__device__ float g_sw, g_zw;
__device__ unsigned g_cmin[64], g_cmax[64];
__device__ float g_s3[64], g_z3[64];

// ---------------------------------------------------------------------------
__device__ __forceinline__ unsigned f2ord(float f) {
    unsigned u = __float_as_uint(f);
    return (u & 0x80000000u) ? ~u : (u | 0x80000000u);
}
__device__ __forceinline__ float ord2f(unsigned u) {
    return __uint_as_float((u & 0x80000000u) ? (u & 0x7FFFFFFFu) : ~u);
}
__device__ __forceinline__ uint32_t smem_u32(const void* p) {
    uint32_t a;
    asm("{ .reg .u64 t; cvta.to.shared.u64 t, %1; cvt.u32.u64 %0, t; }"
        : "=r"(a) : "l"(p));
    return a;
}
__device__ __forceinline__ void cp16(uint32_t dst, const void* src) {
    asm volatile("cp.async.cg.shared.global [%0], [%1], 16;"
                 :: "r"(dst), "l"(src) : "memory");
}
__device__ __forceinline__ void cp_commit() {
    asm volatile("cp.async.commit_group;" ::: "memory");
}
template <int N>
__device__ __forceinline__ void cp_wait() {
    asm volatile("cp.async.wait_group %0;" :: "n"(N) : "memory");
}
__device__ __forceinline__ void ldsm4(uint32_t* r, uint32_t addr) {
    asm volatile("ldmatrix.sync.aligned.m8n8.x4.shared.b16 {%0,%1,%2,%3}, [%4];"
                 : "=r"(r[0]), "=r"(r[1]), "=r"(r[2]), "=r"(r[3]) : "r"(addr));
}
__device__ __forceinline__ void imma_s8(int* d, const uint32_t* a,
                                        uint32_t b0, uint32_t b1) {
    asm("mma.sync.aligned.m16n8k32.row.col.s32.s8.s8.s32 "
        "{%0,%1,%2,%3}, {%4,%5,%6,%7}, {%8,%9}, {%0,%1,%2,%3};"
        : "+r"(d[0]), "+r"(d[1]), "+r"(d[2]), "+r"(d[3])
        : "r"(a[0]), "r"(a[1]), "r"(a[2]), "r"(a[3]), "r"(b0), "r"(b1));
}
__device__ __forceinline__ void imma_u8(int* d, const uint32_t* a,
                                        uint32_t b0, uint32_t b1) {
    asm("mma.sync.aligned.m16n8k32.row.col.s32.u8.s8.s32 "
        "{%0,%1,%2,%3}, {%4,%5,%6,%7}, {%8,%9}, {%0,%1,%2,%3};"
        : "+r"(d[0]), "+r"(d[1]), "+r"(d[2]), "+r"(d[3])
        : "r"(a[0]), "r"(a[1]), "r"(a[2]), "r"(a[3]), "r"(b0), "r"(b1));
}

// ---------------------------------------------------------------------------
__global__ void init_scratch_kernel() {
    int t = threadIdx.x;
    if (t == 0) { g_wmin_u = 0xFFFFFFFFu; g_wmax_u = 0u; }
    if (t < 64) { g_cmin[t] = 0xFFFFFFFFu; g_cmax[t] = 0u; }
}

// ---------------------------------------------------------------------------
__global__ void wminmax_kernel(const float* __restrict__ w, long n4) {
    float mn = FLT_BIG, mx = -FLT_BIG;
    long stride = (long)gridDim.x * blockDim.x;
    for (long i = (long)blockIdx.x * blockDim.x + threadIdx.x; i < n4; i += stride) {
        float4 v = ((const float4*)w)[i];
        mn = fminf(mn, fminf(fminf(v.x, v.y), fminf(v.z, v.w)));
        mx = fmaxf(mx, fmaxf(fmaxf(v.x, v.y), fmaxf(v.z, v.w)));
    }
    #pragma unroll
    for (int o = 16; o; o >>= 1) {
        mn = fminf(mn, __shfl_down_sync(0xFFFFFFFFu, mn, o));
        mx = fmaxf(mx, __shfl_down_sync(0xFFFFFFFFu, mx, o));
    }
    __shared__ float smn[8], smx[8];
    int lane = threadIdx.x & 31, wrp = threadIdx.x >> 5;
    if (!lane) { smn[wrp] = mn; smx[wrp] = mx; }
    __syncthreads();
    if (threadIdx.x == 0) {
        for (int i = 1; i < (int)(blockDim.x >> 5); i++) {
            mn = fminf(mn, smn[i]); mx = fmaxf(mx, smx[i]);
        }
        atomicMin(&g_wmin_u, f2ord(mn));
        atomicMax(&g_wmax_u, f2ord(mx));
    }
}

__global__ void wparams_kernel() {
    float mn = ord2f(g_wmin_u), mx = ord2f(g_wmax_u);
    float s = __fdiv_rn(mx - mn, 255.0f);
    g_sw = s;
    g_zw = -rintf(__fdiv_rn(mn, s));
}

// weights -> B8 = q - 128 (exact s8)
__global__ void wquant_kernel(const float* __restrict__ w, long n4) {
    float s = g_sw, zp = g_zw;
    long stride = (long)gridDim.x * blockDim.x;
    for (long i = (long)blockIdx.x * blockDim.x + threadIdx.x; i < n4; i += stride) {
        float4 v = ((const float4*)w)[i];
        int q0 = (int)fminf(fmaxf(rintf(__fdiv_rn(v.x, s) + zp), 0.0f), 255.0f) - 128;
        int q1 = (int)fminf(fmaxf(rintf(__fdiv_rn(v.y, s) + zp), 0.0f), 255.0f) - 128;
        int q2 = (int)fminf(fmaxf(rintf(__fdiv_rn(v.z, s) + zp), 0.0f), 255.0f) - 128;
        int q3 = (int)fminf(fmaxf(rintf(__fdiv_rn(v.w, s) + zp), 0.0f), 255.0f) - 128;
        ((unsigned*)g_b8)[i] = (q0 & 255) | ((q1 & 255) << 8)
                             | ((q2 & 255) << 16) | ((q3 & 255) << 24);
    }
}

// x -> digits d1 (s8), d0 (u8), per-row int sum. One warp per row.
__global__ void xdigits_kernel(const float* __restrict__ x, int IND, int nrows) {
    int w = (blockIdx.x * blockDim.x + threadIdx.x) >> 5;
    int lane = threadIdx.x & 31;
    if (w >= nrows) return;
    const float4* xr = (const float4*)(x + (size_t)w * IND);
    unsigned* o1 = (unsigned*)g_d1 + (size_t)w * (IND / 4);
    unsigned* o0 = (unsigned*)g_d0 + (size_t)w * (IND / 4);
    int sum = 0;
    for (int i = lane; i < IND / 4; i += 32) {
        float4 v = xr[i];
        int x0 = min(max(__float2int_rn(v.x * XSC), -32768), 32767);
        int x1 = min(max(__float2int_rn(v.y * XSC), -32768), 32767);
        int x2 = min(max(__float2int_rn(v.z * XSC), -32768), 32767);
        int x3 = min(max(__float2int_rn(v.w * XSC), -32768), 32767);
        sum += x0 + x1 + x2 + x3;
        o1[i] = ((x0 >> 8) & 255) | (((x1 >> 8) & 255) << 8)
              | (((x2 >> 8) & 255) << 16) | (((x3 >> 8) & 255) << 24);
        o0[i] = (x0 & 255) | ((x1 & 255) << 8)
              | ((x2 & 255) << 16) | ((x3 & 255) << 24);
    }
    #pragma unroll
    for (int o = 16; o; o >>= 1) sum += __shfl_down_sync(0xFFFFFFFFu, sum, o);
    if (lane == 0) g_rs[w] = (float)sum;
}

// ---------------------------------------------------------------------------
// Int8 GEMM: acc1 = d1@B8 (s8.s8), acc0 = d0@B8 (u8.s8), both exact s32.
// CTA 128x128, BK=64 bytes, 8 warps 32x64, 4-stage cp.async pipeline.
// smem rows 64B, chunk16 j swizzled j ^ ((row>>1)&3) (conflict-free ldmatrix).
// ---------------------------------------------------------------------------
__global__ __launch_bounds__(NTH, 1)
void gemm_i8_kernel(const float* __restrict__ bias, float* __restrict__ out,
                    int IND, int ND, int nPerCluster) {
    extern __shared__ char smc[];
    const int tid = threadIdx.x;
    const int lane = tid & 31, wid = tid >> 5;
    const int q = lane & 3, r4 = lane >> 2;
    const int wm = wid & 3, wn = wid >> 2;   // 4x2 warp grid, warp 32x64
    const int Rw = wm * 32, Cw = wn * 64;
    const int m0 = blockIdx.y * BM;
    const int n0 = blockIdx.x * BN;
    const uint32_t sb = smem_u32(smc);

    int acc1[2][8][4], acc0[2][8][4];
    #pragma unroll
    for (int mi = 0; mi < 2; mi++)
        #pragma unroll
        for (int nb = 0; nb < 8; nb++)
            #pragma unroll
            for (int e = 0; e < 4; e++) { acc1[mi][nb][e] = 0; acc0[mi][nb][e] = 0; }

    // cp.async: 512 16B rows-chunks per tensor, 2 per thread per tensor
    auto issue = [&](int ck, int s) {
        const uint32_t st = sb + s * STG_B;
        #pragma unroll
        for (int i = 0; i < 2; i++) {
            int c = tid + i * 256;
            int r = c >> 2, g = c & 3;
            uint32_t d = (uint32_t)(r * 64 + ((g ^ ((r >> 1) & 3)) << 4));
            size_t go = (size_t)ck * 64 + g * 16;
            cp16(st + d,          g_d1 + (size_t)(m0 + r) * IND + go);
            cp16(st + OFF_D0 + d, g_d0 + (size_t)(m0 + r) * IND + go);
            cp16(st + OFF_B + d,  g_b8 + (size_t)(n0 + r) * IND + go);
        }
    };

    // ldmatrix lane bases
    const int arow = Rw + ((lane >> 3) & 1) * 8 + (lane & 7);  // + mi*16
    const int ajs  = lane >> 4;                                 // j low bit
    const int brow = Cw + ((lane >> 4) & 1) * 8 + (lane & 7);  // + p*16
    const int bjs  = (lane >> 3) & 1;

    auto compute = [&](int s) {
        const uint32_t st = sb + s * STG_B;
        #pragma unroll
        for (int kq = 0; kq < 2; kq++) {
            uint32_t bb[4][4];
            #pragma unroll
            for (int p = 0; p < 4; p++) {
                int r = brow + p * 16;
                int j = kq * 2 + bjs;
                uint32_t off = (uint32_t)(r * 64 + ((j ^ ((r >> 1) & 3)) << 4));
                ldsm4(bb[p], st + OFF_B + off);
            }
            #pragma unroll
            for (int mi = 0; mi < 2; mi++) {
                int r = arow + mi * 16;
                int j = kq * 2 + ajs;
                uint32_t off = (uint32_t)(r * 64 + ((j ^ ((r >> 1) & 3)) << 4));
                uint32_t a[4];
                ldsm4(a, st + off);
                #pragma unroll
                for (int p = 0; p < 4; p++) {
                    imma_s8(acc1[mi][p * 2],     a, bb[p][0], bb[p][1]);
                    imma_s8(acc1[mi][p * 2 + 1], a, bb[p][2], bb[p][3]);
                }
                ldsm4(a, st + OFF_D0 + off);
                #pragma unroll
                for (int p = 0; p < 4; p++) {
                    imma_u8(acc0[mi][p * 2],     a, bb[p][0], bb[p][1]);
                    imma_u8(acc0[mi][p * 2 + 1], a, bb[p][2], bb[p][3]);
                }
            }
        }
    };

    const int NCH = IND / 64;   // 64
    issue(0, 0); cp_commit();
    issue(1, 1); cp_commit();
    issue(2, 2); cp_commit();

    for (int k = 0; k < NCH; k++) {
        cp_wait<2>();
        __syncthreads();
        compute(k & (NSTG - 1));
        if (k + 3 < NCH) issue(k + 3, (k + 3) & (NSTG - 1));
        cp_commit();   // commit every iter (possibly empty) to keep group count
    }

    // epilogue: combine digits exactly, scale, +rowsum corr, +bias, minmax
    const float sv = g_sw, zv = g_zw;
    const double dsc = (double)sv / 4096.0;
    const float crs = (float)((double)sv * (128.0 - (double)zv) / 4096.0);

    float lmin = FLT_BIG, lmax = -FLT_BIG;
    float2 bz[8];
    #pragma unroll
    for (int nb = 0; nb < 8; nb++)
        bz[nb] = *(const float2*)(bias + n0 + Cw + nb * 8 + 2 * q);

    #pragma unroll
    for (int mi = 0; mi < 2; mi++) {
        int r0 = m0 + Rw + mi * 16 + r4;
        float c0 = crs * g_rs[r0];
        float c8 = crs * g_rs[r0 + 8];
        #pragma unroll
        for (int nb = 0; nb < 8; nb++) {
            int col = n0 + Cw + nb * 8 + 2 * q;
            double v0 = fma((double)acc1[mi][nb][0], 256.0, (double)acc0[mi][nb][0]);
            double v1 = fma((double)acc1[mi][nb][1], 256.0, (double)acc0[mi][nb][1]);
            double v2 = fma((double)acc1[mi][nb][2], 256.0, (double)acc0[mi][nb][2]);
            double v3 = fma((double)acc1[mi][nb][3], 256.0, (double)acc0[mi][nb][3]);
            float f0 = (float)(v0 * dsc) + c0 + bz[nb].x;
            float f1 = (float)(v1 * dsc) + c0 + bz[nb].y;
            float f2 = (float)(v2 * dsc) + c8 + bz[nb].x;
            float f3 = (float)(v3 * dsc) + c8 + bz[nb].y;
            lmin = fminf(lmin, fminf(fminf(f0, f1), fminf(f2, f3)));
            lmax = fmaxf(lmax, fmaxf(fmaxf(f0, f1), fmaxf(f2, f3)));
            *(float2*)(out + (size_t)r0 * ND + col)       = make_float2(f0, f1);
            *(float2*)(out + (size_t)(r0 + 8) * ND + col) = make_float2(f2, f3);
        }
    }

    #pragma unroll
    for (int o = 16; o; o >>= 1) {
        lmin = fminf(lmin, __shfl_down_sync(0xFFFFFFFFu, lmin, o));
        lmax = fmaxf(lmax, __shfl_down_sync(0xFFFFFFFFu, lmax, o));
    }
    __shared__ float smn[8], smx[8];
    if (!lane) { smn[wid] = lmin; smx[wid] = lmax; }
    __syncthreads();
    if (tid == 0) {
        float mn = smn[0], mx = smx[0];
        #pragma unroll
        for (int i = 1; i < 8; i++) { mn = fminf(mn, smn[i]); mx = fmaxf(mx, smx[i]); }
        int cl = m0 / nPerCluster;
        atomicMin(&g_cmin[cl], f2ord(mn));
        atomicMax(&g_cmax[cl], f2ord(mx));
    }
}

// ---------------------------------------------------------------------------
__global__ void range_kernel(const float* __restrict__ act_range,
                             const int* __restrict__ cinfo,
                             float* __restrict__ rout, int Kc) {
    int t = threadIdx.x;
    if (t < 2 * Kc) rout[t] = act_range[t];
    __syncthreads();
    if (t < Kc) {
        int c = cinfo[2 * t];
        float mn = ord2f(g_cmin[t]);
        float mx = ord2f(g_cmax[t]);
        float om = act_range[2 * c], oM = act_range[2 * c + 1];
        const float SM  = 0.999f;
        const float OMS = (float)(1.0 - 0.999);
        float nm = om * SM + mn * OMS;
        float nM = oM * SM + mx * OMS;
        rout[2 * c]     = nm;
        rout[2 * c + 1] = nM;
        float s = __fdiv_rn(nM - nm, 255.0f);
        g_s3[t] = s;
        g_z3[t] = -rintf(__fdiv_rn(nm, s));
    }
}

// ---------------------------------------------------------------------------
__global__ void quant_out_kernel(float* __restrict__ out, long total4,
                                 int ND, int nPerCluster) {
    long stride = (long)gridDim.x * blockDim.x;
    for (long i = (long)blockIdx.x * blockDim.x + threadIdx.x; i < total4; i += stride) {
        long e = i * 4;
        int row = (int)(e / ND);
        int g = row / nPerCluster;
        float s = g_s3[g], zp = g_z3[g];
        float4 v = ((float4*)out)[i];
        v.x = (fminf(fmaxf(rintf(__fdiv_rn(v.x, s) + zp), 0.0f), 255.0f) - zp) * s;
        v.y = (fminf(fmaxf(rintf(__fdiv_rn(v.y, s) + zp), 0.0f), 255.0f) - zp) * s;
        v.z = (fminf(fmaxf(rintf(__fdiv_rn(v.z, s) + zp), 0.0f), 255.0f) - zp) * s;
        v.w = (fminf(fmaxf(rintf(__fdiv_rn(v.w, s) + zp), 0.0f), 255.0f) - zp) * s;
        ((float4*)out)[i] = v;
    }
}

// ---------------------------------------------------------------------------
extern "C" void kernel_launch(void* const* d_in, const int* in_sizes, int n_in,
                              void* d_out, int out_size) {
    const float* x         = (const float*)d_in[0];
    const float* weight    = (const float*)d_in[1];
    const float* bias      = (const float*)d_in[2];
    const float* act_range = (const float*)d_in[3];
    const int*   cinfo     = (const int*)d_in[4];

    int OUT = in_sizes[2];             // bias length
    int IN  = in_sizes[1] / OUT;       // weight is [OUT, IN]
    int B   = in_sizes[0] / IN;        // x is [B, IN]
    int Kc  = in_sizes[3] / 2;         // act_range [K, 2]
    int nPer = B / Kc;

    float* out  = (float*)d_out;
    float* rout = out + (size_t)B * OUT;

    long w4 = (long)OUT * IN / 4;
    long o4 = (long)B * OUT / 4;

    init_scratch_kernel<<<1, 64>>>();
    wminmax_kernel<<<1024, 256>>>(weight, w4);
    wparams_kernel<<<1, 1>>>();
    wquant_kernel<<<2048, 256>>>(weight, w4);
    xdigits_kernel<<<(B * 32 + 255) / 256, 256>>>(x, IN, B);

    cudaFuncSetAttribute(gemm_i8_kernel,
                         cudaFuncAttributeMaxDynamicSharedMemorySize, SMEM_BYTES);
    dim3 grid(OUT / BN, B / BM);
    gemm_i8_kernel<<<grid, NTH, SMEM_BYTES>>>(bias, out, IN, OUT, nPer);

    range_kernel<<<1, 128>>>(act_range, cinfo, rout, Kc);
    quant_out_kernel<<<2048, 256>>>(out, o4, OUT, nPer);
}

// round 10
// speedup vs baseline: 2.7401x; 2.7401x over previous
#include <cuda_runtime.h>
#include <cuda_bf16.h>
#include <cstdint>

// ---------------------------------------------------------------------------
// PCQLinear: w_q = fakequant(weight, global min/max); out = x @ w_q^T + bias;
// per-cluster min/max -> EMA range update -> fakequant.
//
// GEMM trick: w_q = s*(q - z) with (q - z) small integers -> EXACT in bf16.
// out = s * (x @ Qc^T) + bias, Qc = q - z in bf16 (no B split needed).
// x split into bf16 hi+lo (2 passes), mma.sync m16n8k16 bf16, fp32 accum.
// R10: CTA 128x256, 2x4 warp grid (warp 64x64) to cut smem ldmatrix traffic
// (B-fragment duplication 4x -> 2x), 3-stage cp.async pipeline.
// ---------------------------------------------------------------------------

#define FLT_BIG 3.402823466e38f

#define BM 128
#define BN 256
#define BKB 32                 // k per chunk (bf16 elems) = 64B rows
#define NTH 256
#define STG_B 32768            // AH 8K | AL 8K | B 16K
#define OFF_AL 8192
#define OFF_B  16384
#define NSTG 3
#define SMEM_BYTES (NSTG * STG_B)   // 96 KB

// Scratch (allocation-free: __device__ globals)
__device__ __nv_bfloat16 g_wqc[4096l * 4096];    // (q - z), exact ints in bf16
__device__ __nv_bfloat16 g_xh[10240l * 4096];
__device__ __nv_bfloat16 g_xl[10240l * 4096];
__device__ unsigned g_wmin_u, g_wmax_u;
__device__ float g_sw, g_zw;
__device__ unsigned g_cmin[64], g_cmax[64];
__device__ float g_s3[64], g_z3[64];

// ---------------------------------------------------------------------------
__device__ __forceinline__ unsigned f2ord(float f) {
    unsigned u = __float_as_uint(f);
    return (u & 0x80000000u) ? ~u : (u | 0x80000000u);
}
__device__ __forceinline__ float ord2f(unsigned u) {
    return __uint_as_float((u & 0x80000000u) ? (u & 0x7FFFFFFFu) : ~u);
}
__device__ __forceinline__ uint32_t smem_u32(const void* p) {
    uint32_t a;
    asm("{ .reg .u64 t; cvta.to.shared.u64 t, %1; cvt.u32.u64 %0, t; }"
        : "=r"(a) : "l"(p));
    return a;
}
__device__ __forceinline__ void cp16(uint32_t dst, const void* src) {
    asm volatile("cp.async.cg.shared.global [%0], [%1], 16;"
                 :: "r"(dst), "l"(src) : "memory");
}
__device__ __forceinline__ void cp_commit() {
    asm volatile("cp.async.commit_group;" ::: "memory");
}
template <int N>
__device__ __forceinline__ void cp_wait() {
    asm volatile("cp.async.wait_group %0;" :: "n"(N) : "memory");
}
__device__ __forceinline__ void ldsm4(uint32_t* r, uint32_t addr) {
    asm volatile("ldmatrix.sync.aligned.m8n8.x4.shared.b16 {%0,%1,%2,%3}, [%4];"
                 : "=r"(r[0]), "=r"(r[1]), "=r"(r[2]), "=r"(r[3]) : "r"(addr));
}
__device__ __forceinline__ void mma16(float* d, const uint32_t* a,
                                      uint32_t b0, uint32_t b1) {
    asm("mma.sync.aligned.m16n8k16.row.col.f32.bf16.bf16.f32 "
        "{%0,%1,%2,%3}, {%4,%5,%6,%7}, {%8,%9}, {%0,%1,%2,%3};"
        : "+f"(d[0]), "+f"(d[1]), "+f"(d[2]), "+f"(d[3])
        : "r"(a[0]), "r"(a[1]), "r"(a[2]), "r"(a[3]), "r"(b0), "r"(b1));
}

// ---------------------------------------------------------------------------
__global__ void init_scratch_kernel() {
    int t = threadIdx.x;
    if (t == 0) { g_wmin_u = 0xFFFFFFFFu; g_wmax_u = 0u; }
    if (t < 64) { g_cmin[t] = 0xFFFFFFFFu; g_cmax[t] = 0u; }
}

// ---------------------------------------------------------------------------
__global__ void wminmax_kernel(const float* __restrict__ w, long n4) {
    float mn = FLT_BIG, mx = -FLT_BIG;
    long stride = (long)gridDim.x * blockDim.x;
    for (long i = (long)blockIdx.x * blockDim.x + threadIdx.x; i < n4; i += stride) {
        float4 v = ((const float4*)w)[i];
        mn = fminf(mn, fminf(fminf(v.x, v.y), fminf(v.z, v.w)));
        mx = fmaxf(mx, fmaxf(fmaxf(v.x, v.y), fmaxf(v.z, v.w)));
    }
    #pragma unroll
    for (int o = 16; o; o >>= 1) {
        mn = fminf(mn, __shfl_down_sync(0xFFFFFFFFu, mn, o));
        mx = fmaxf(mx, __shfl_down_sync(0xFFFFFFFFu, mx, o));
    }
    __shared__ float smn[8], smx[8];
    int lane = threadIdx.x & 31, wrp = threadIdx.x >> 5;
    if (!lane) { smn[wrp] = mn; smx[wrp] = mx; }
    __syncthreads();
    if (threadIdx.x == 0) {
        for (int i = 1; i < (int)(blockDim.x >> 5); i++) {
            mn = fminf(mn, smn[i]); mx = fmaxf(mx, smx[i]);
        }
        atomicMin(&g_wmin_u, f2ord(mn));
        atomicMax(&g_wmax_u, f2ord(mx));
    }
}

__global__ void wparams_kernel() {
    float mn = ord2f(g_wmin_u), mx = ord2f(g_wmax_u);
    float s = __fdiv_rn(mx - mn, 255.0f);
    g_sw = s;
    g_zw = -rintf(__fdiv_rn(mn, s));
}

// quantize weights to centered integer codes Qc = clip(round(w/s+z),0,255)-z,
// stored exactly as bf16 (|Qc| <= 255).
__global__ void wquant_kernel(const float* __restrict__ w, long n4) {
    float s = g_sw, zp = g_zw;
    long stride = (long)gridDim.x * blockDim.x;
    for (long i = (long)blockIdx.x * blockDim.x + threadIdx.x; i < n4; i += stride) {
        float4 v = ((const float4*)w)[i];
        float q0 = fminf(fmaxf(rintf(__fdiv_rn(v.x, s) + zp), 0.0f), 255.0f) - zp;
        float q1 = fminf(fmaxf(rintf(__fdiv_rn(v.y, s) + zp), 0.0f), 255.0f) - zp;
        float q2 = fminf(fmaxf(rintf(__fdiv_rn(v.z, s) + zp), 0.0f), 255.0f) - zp;
        float q3 = fminf(fmaxf(rintf(__fdiv_rn(v.w, s) + zp), 0.0f), 255.0f) - zp;
        __nv_bfloat162* o = (__nv_bfloat162*)g_wqc + i * 2;
        o[0] = __nv_bfloat162(__float2bfloat16(q0), __float2bfloat16(q1));
        o[1] = __nv_bfloat162(__float2bfloat16(q2), __float2bfloat16(q3));
    }
}

// split x into bf16 hi + lo
__global__ void xsplit_kernel(const float* __restrict__ x, long n4) {
    long stride = (long)gridDim.x * blockDim.x;
    for (long i = (long)blockIdx.x * blockDim.x + threadIdx.x; i < n4; i += stride) {
        float4 v = ((const float4*)x)[i];
        __nv_bfloat16 h0 = __float2bfloat16(v.x);
        __nv_bfloat16 h1 = __float2bfloat16(v.y);
        __nv_bfloat16 h2 = __float2bfloat16(v.z);
        __nv_bfloat16 h3 = __float2bfloat16(v.w);
        __nv_bfloat162* oh = (__nv_bfloat162*)g_xh + i * 2;
        oh[0] = __nv_bfloat162(h0, h1);
        oh[1] = __nv_bfloat162(h2, h3);
        __nv_bfloat162* ol = (__nv_bfloat162*)g_xl + i * 2;
        ol[0] = __nv_bfloat162(__float2bfloat16(v.x - __bfloat162float(h0)),
                               __float2bfloat16(v.y - __bfloat162float(h1)));
        ol[1] = __nv_bfloat162(__float2bfloat16(v.z - __bfloat162float(h2)),
                               __float2bfloat16(v.w - __bfloat162float(h3)));
    }
}

// ---------------------------------------------------------------------------
// bf16 2-pass GEMM: out = s*( (xh+xl) @ Qc^T ) + bias.
// CTA 128x256, BK=32 bf16 (64B rows), 3-stage cp.async, ldmatrix frags.
// Warp grid 2x4 (warp 64x64). smem swizzle: chunk' = chunk ^ ((row>>1)&3).
// ---------------------------------------------------------------------------
__global__ __launch_bounds__(NTH, 1)
void gemm_bf16_kernel(const float* __restrict__ bias, float* __restrict__ out,
                      int IND, int ND, int nPerCluster) {
    extern __shared__ char smc[];
    const int tid = threadIdx.x;
    const int lane = tid & 31, wid = tid >> 5;
    const int q = lane & 3, r4 = lane >> 2;
    const int wm = wid & 1, wn = wid >> 1;   // 2x4 warp grid, warp 64x64
    const int Rw = wm * 64, Cw = wn * 64;
    const int m0 = blockIdx.y * BM;
    const int n0 = blockIdx.x * BN;
    const uint32_t sb = smem_u32(smc);

    float acc[4][8][4];
    #pragma unroll
    for (int mi = 0; mi < 4; mi++)
        #pragma unroll
        for (int nb = 0; nb < 8; nb++)
            #pragma unroll
            for (int e = 0; e < 4; e++) acc[mi][nb][e] = 0.0f;

    // cp.async issue: A rows 128 (hi+lo, 2 cp16/thread each), B rows 256 (4/thread)
    auto issue = [&](int ck, int s) {
        const uint32_t st = sb + s * STG_B;
        const long kk = (long)ck * BKB;
        #pragma unroll
        for (int i = 0; i < 2; i++) {
            int c = tid + i * 256;
            int r = c >> 2, g = c & 3;
            uint32_t d = (uint32_t)(r * 64 + ((g ^ ((r >> 1) & 3)) << 4));
            long goff = kk + g * 8;
            cp16(st + d,          g_xh + (size_t)(m0 + r) * IND + goff);
            cp16(st + OFF_AL + d, g_xl + (size_t)(m0 + r) * IND + goff);
        }
        #pragma unroll
        for (int i = 0; i < 4; i++) {
            int c = tid + i * 256;
            int r = c >> 2, g = c & 3;
            uint32_t d = (uint32_t)(r * 64 + ((g ^ ((r >> 1) & 3)) << 4));
            cp16(st + OFF_B + d, g_wqc + (size_t)(n0 + r) * IND + kk + g * 8);
        }
    };

    // ldmatrix lane bases (identical mappings to validated R8 kernel)
    const int arow_base = (lane & 7) + ((lane >> 3) & 1) * 8;
    const int ag = lane >> 4;
    const int brow_base = lane & 7;
    const int bg = lane >> 3;

    auto compute = [&](int s) {
        const uint32_t st = sb + s * STG_B;
        uint32_t ah[4][2][4], al[4][2][4];
        #pragma unroll
        for (int mi = 0; mi < 4; mi++)
            #pragma unroll
            for (int at = 0; at < 2; at++) {
                int r = Rw + mi * 16 + arow_base;
                int g = at * 2 + ag;
                uint32_t off = (uint32_t)(r * 64 + ((g ^ ((r >> 1) & 3)) << 4));
                ldsm4(ah[mi][at], st + off);
                ldsm4(al[mi][at], st + OFF_AL + off);
            }
        #pragma unroll
        for (int nb = 0; nb < 8; nb++) {
            int r = Cw + nb * 8 + brow_base;
            uint32_t off = (uint32_t)(r * 64 + ((bg ^ ((r >> 1) & 3)) << 4));
            uint32_t b[4];
            ldsm4(b, st + OFF_B + off);
            #pragma unroll
            for (int mi = 0; mi < 4; mi++) {
                float* d = acc[mi][nb];
                mma16(d, ah[mi][0], b[0], b[1]);
                mma16(d, al[mi][0], b[0], b[1]);
                mma16(d, ah[mi][1], b[2], b[3]);
                mma16(d, al[mi][1], b[2], b[3]);
            }
        }
    };

    const int NCH = IND / BKB;   // 128
    issue(0, 0); cp_commit();
    issue(1, 1); cp_commit();
    issue(2, 2); cp_commit();

    int snext = 0;  // stage of chunk k
    for (int k = 0; k < NCH; k++) {
        cp_wait<2>();
        __syncthreads();
        compute(snext);
        __syncthreads();
        if (k + 3 < NCH) issue(k + 3, snext);
        cp_commit();   // commit every iter (possibly empty) to keep group count
        snext = (snext + 1 == NSTG) ? 0 : snext + 1;
    }

    // epilogue: scale by s, +bias, per-cluster min/max, direct stores
    const float sf = g_sw;
    float lmin = FLT_BIG, lmax = -FLT_BIG;
    float2 bz[8];
    #pragma unroll
    for (int nb = 0; nb < 8; nb++)
        bz[nb] = *(const float2*)(bias + n0 + Cw + nb * 8 + 2 * q);

    #pragma unroll
    for (int mi = 0; mi < 4; mi++) {
        int r0 = m0 + Rw + mi * 16 + r4;
        #pragma unroll
        for (int nb = 0; nb < 8; nb++) {
            int col = n0 + Cw + nb * 8 + 2 * q;
            float v0 = sf * acc[mi][nb][0] + bz[nb].x;
            float v1 = sf * acc[mi][nb][1] + bz[nb].y;
            float v2 = sf * acc[mi][nb][2] + bz[nb].x;
            float v3 = sf * acc[mi][nb][3] + bz[nb].y;
            lmin = fminf(lmin, fminf(fminf(v0, v1), fminf(v2, v3)));
            lmax = fmaxf(lmax, fmaxf(fmaxf(v0, v1), fmaxf(v2, v3)));
            *(float2*)(out + (size_t)r0 * ND + col)       = make_float2(v0, v1);
            *(float2*)(out + (size_t)(r0 + 8) * ND + col) = make_float2(v2, v3);
        }
    }

    #pragma unroll
    for (int o = 16; o; o >>= 1) {
        lmin = fminf(lmin, __shfl_down_sync(0xFFFFFFFFu, lmin, o));
        lmax = fmaxf(lmax, __shfl_down_sync(0xFFFFFFFFu, lmax, o));
    }
    __shared__ float smn[8], smx[8];
    if (!lane) { smn[wid] = lmin; smx[wid] = lmax; }
    __syncthreads();
    if (tid == 0) {
        float mn = smn[0], mx = smx[0];
        #pragma unroll
        for (int i = 1; i < 8; i++) { mn = fminf(mn, smn[i]); mx = fmaxf(mx, smx[i]); }
        int cl = m0 / nPerCluster;
        atomicMin(&g_cmin[cl], f2ord(mn));
        atomicMax(&g_cmax[cl], f2ord(mx));
    }
}

// ---------------------------------------------------------------------------
__global__ void range_kernel(const float* __restrict__ act_range,
                             const int* __restrict__ cinfo,
                             float* __restrict__ rout, int Kc) {
    int t = threadIdx.x;
    if (t < 2 * Kc) rout[t] = act_range[t];
    __syncthreads();
    if (t < Kc) {
        int c = cinfo[2 * t];
        float mn = ord2f(g_cmin[t]);
        float mx = ord2f(g_cmax[t]);
        float om = act_range[2 * c], oM = act_range[2 * c + 1];
        const float SM  = 0.999f;
        const float OMS = (float)(1.0 - 0.999);
        float nm = om * SM + mn * OMS;
        float nM = oM * SM + mx * OMS;
        rout[2 * c]     = nm;
        rout[2 * c + 1] = nM;
        float s = __fdiv_rn(nM - nm, 255.0f);
        g_s3[t] = s;
        g_z3[t] = -rintf(__fdiv_rn(nm, s));
    }
}

// ---------------------------------------------------------------------------
__global__ void quant_out_kernel(float* __restrict__ out, long total4,
                                 int ND, int nPerCluster) {
    long stride = (long)gridDim.x * blockDim.x;
    for (long i = (long)blockIdx.x * blockDim.x + threadIdx.x; i < total4; i += stride) {
        long e = i * 4;
        int row = (int)(e / ND);
        int g = row / nPerCluster;
        float s = g_s3[g], zp = g_z3[g];
        float4 v = ((float4*)out)[i];
        v.x = (fminf(fmaxf(rintf(__fdiv_rn(v.x, s) + zp), 0.0f), 255.0f) - zp) * s;
        v.y = (fminf(fmaxf(rintf(__fdiv_rn(v.y, s) + zp), 0.0f), 255.0f) - zp) * s;
        v.z = (fminf(fmaxf(rintf(__fdiv_rn(v.z, s) + zp), 0.0f), 255.0f) - zp) * s;
        v.w = (fminf(fmaxf(rintf(__fdiv_rn(v.w, s) + zp), 0.0f), 255.0f) - zp) * s;
        ((float4*)out)[i] = v;
    }
}

// ---------------------------------------------------------------------------
extern "C" void kernel_launch(void* const* d_in, const int* in_sizes, int n_in,
                              void* d_out, int out_size) {
    const float* x         = (const float*)d_in[0];
    const float* weight    = (const float*)d_in[1];
    const float* bias      = (const float*)d_in[2];
    const float* act_range = (const float*)d_in[3];
    const int*   cinfo     = (const int*)d_in[4];

    int OUT = in_sizes[2];             // bias length
    int IN  = in_sizes[1] / OUT;       // weight is [OUT, IN]
    int B   = in_sizes[0] / IN;        // x is [B, IN]
    int Kc  = in_sizes[3] / 2;         // act_range [K, 2]
    int nPer = B / Kc;

    float* out  = (float*)d_out;
    float* rout = out + (size_t)B * OUT;

    long w4 = (long)OUT * IN / 4;
    long x4 = (long)B * IN / 4;
    long o4 = (long)B * OUT / 4;

    init_scratch_kernel<<<1, 64>>>();
    wminmax_kernel<<<1024, 256>>>(weight, w4);
    wparams_kernel<<<1, 1>>>();
    wquant_kernel<<<2048, 256>>>(weight, w4);
    xsplit_kernel<<<4096, 256>>>(x, x4);

    cudaFuncSetAttribute(gemm_bf16_kernel,
                         cudaFuncAttributeMaxDynamicSharedMemorySize, SMEM_BYTES);
    dim3 grid(OUT / BN, B / BM);
    gemm_bf16_kernel<<<grid, NTH, SMEM_BYTES>>>(bias, out, IN, OUT, nPer);

    range_kernel<<<1, 128>>>(act_range, cinfo, rout, Kc);
    quant_out_kernel<<<2048, 256>>>(out, o4, OUT, nPer);
}

// round 12
// speedup vs baseline: 3.1899x; 1.1642x over previous
#include <cuda_runtime.h>
#include <cuda_bf16.h>
#include <cstdint>

// ---------------------------------------------------------------------------
// PCQLinear: w_q = fakequant(weight, global min/max); out = x @ w_q^T + bias;
// per-cluster min/max -> EMA range update -> fakequant.
//
// GEMM trick: w_q = s*(q - z) with (q - z) small integers -> EXACT in bf16.
// out = s * (x @ Qc^T) + bias, Qc = q - z in bf16 (no B split needed).
// x split into bf16 hi+lo (2 passes), mma.sync m16n8k16 bf16, fp32 accum.
// R11: R8 config (128x128, 4x2 warps, 2 CTA/SM) + 4-stage cp.async ring with
// single __syncthreads per chunk (CUTLASS ordering).
// ---------------------------------------------------------------------------

#define FLT_BIG 3.402823466e38f

#define BM 128
#define BN 128
#define BKB 32                 // k per chunk (bf16 elems) = 64B rows
#define NTH 256
#define STG_B 24576            // AH 8K | AL 8K | B 8K
#define OFF_AL 8192
#define OFF_B  16384
#define NSTG 4
#define SMEM_BYTES (NSTG * STG_B)   // 96 KB (x2 CTAs = 192 KB <= 228)

// Scratch (allocation-free: __device__ globals)
__device__ __nv_bfloat16 g_wqc[4096l * 4096];    // (q - z), exact ints in bf16
__device__ __nv_bfloat16 g_xh[10240l * 4096];
__device__ __nv_bfloat16 g_xl[10240l * 4096];
__device__ unsigned g_wmin_u, g_wmax_u;
__device__ float g_sw, g_zw;
__device__ unsigned g_cmin[64], g_cmax[64];
__device__ float g_s3[64], g_z3[64];

// ---------------------------------------------------------------------------
__device__ __forceinline__ unsigned f2ord(float f) {
    unsigned u = __float_as_uint(f);
    return (u & 0x80000000u) ? ~u : (u | 0x80000000u);
}
__device__ __forceinline__ float ord2f(unsigned u) {
    return __uint_as_float((u & 0x80000000u) ? (u & 0x7FFFFFFFu) : ~u);
}
__device__ __forceinline__ uint32_t smem_u32(const void* p) {
    uint32_t a;
    asm("{ .reg .u64 t; cvta.to.shared.u64 t, %1; cvt.u32.u64 %0, t; }"
        : "=r"(a) : "l"(p));
    return a;
}
__device__ __forceinline__ void cp16(uint32_t dst, const void* src) {
    asm volatile("cp.async.cg.shared.global [%0], [%1], 16;"
                 :: "r"(dst), "l"(src) : "memory");
}
__device__ __forceinline__ void cp_commit() {
    asm volatile("cp.async.commit_group;" ::: "memory");
}
template <int N>
__device__ __forceinline__ void cp_wait() {
    asm volatile("cp.async.wait_group %0;" :: "n"(N) : "memory");
}
__device__ __forceinline__ void ldsm4(uint32_t* r, uint32_t addr) {
    asm volatile("ldmatrix.sync.aligned.m8n8.x4.shared.b16 {%0,%1,%2,%3}, [%4];"
                 : "=r"(r[0]), "=r"(r[1]), "=r"(r[2]), "=r"(r[3]) : "r"(addr));
}
__device__ __forceinline__ void mma16(float* d, const uint32_t* a,
                                      uint32_t b0, uint32_t b1) {
    asm("mma.sync.aligned.m16n8k16.row.col.f32.bf16.bf16.f32 "
        "{%0,%1,%2,%3}, {%4,%5,%6,%7}, {%8,%9}, {%0,%1,%2,%3};"
        : "+f"(d[0]), "+f"(d[1]), "+f"(d[2]), "+f"(d[3])
        : "r"(a[0]), "r"(a[1]), "r"(a[2]), "r"(a[3]), "r"(b0), "r"(b1));
}

// ---------------------------------------------------------------------------
__global__ void init_scratch_kernel() {
    int t = threadIdx.x;
    if (t == 0) { g_wmin_u = 0xFFFFFFFFu; g_wmax_u = 0u; }
    if (t < 64) { g_cmin[t] = 0xFFFFFFFFu; g_cmax[t] = 0u; }
}

// ---------------------------------------------------------------------------
__global__ void wminmax_kernel(const float* __restrict__ w, long n4) {
    float mn = FLT_BIG, mx = -FLT_BIG;
    long stride = (long)gridDim.x * blockDim.x;
    for (long i = (long)blockIdx.x * blockDim.x + threadIdx.x; i < n4; i += stride) {
        float4 v = ((const float4*)w)[i];
        mn = fminf(mn, fminf(fminf(v.x, v.y), fminf(v.z, v.w)));
        mx = fmaxf(mx, fmaxf(fmaxf(v.x, v.y), fmaxf(v.z, v.w)));
    }
    #pragma unroll
    for (int o = 16; o; o >>= 1) {
        mn = fminf(mn, __shfl_down_sync(0xFFFFFFFFu, mn, o));
        mx = fmaxf(mx, __shfl_down_sync(0xFFFFFFFFu, mx, o));
    }
    __shared__ float smn[8], smx[8];
    int lane = threadIdx.x & 31, wrp = threadIdx.x >> 5;
    if (!lane) { smn[wrp] = mn; smx[wrp] = mx; }
    __syncthreads();
    if (threadIdx.x == 0) {
        for (int i = 1; i < (int)(blockDim.x >> 5); i++) {
            mn = fminf(mn, smn[i]); mx = fmaxf(mx, smx[i]);
        }
        atomicMin(&g_wmin_u, f2ord(mn));
        atomicMax(&g_wmax_u, f2ord(mx));
    }
}

__global__ void wparams_kernel() {
    float mn = ord2f(g_wmin_u), mx = ord2f(g_wmax_u);
    float s = __fdiv_rn(mx - mn, 255.0f);
    g_sw = s;
    g_zw = -rintf(__fdiv_rn(mn, s));
}

// quantize weights to centered integer codes Qc = clip(round(w/s+z),0,255)-z,
// stored exactly as bf16 (|Qc| <= 255).
__global__ void wquant_kernel(const float* __restrict__ w, long n4) {
    float s = g_sw, zp = g_zw;
    long stride = (long)gridDim.x * blockDim.x;
    for (long i = (long)blockIdx.x * blockDim.x + threadIdx.x; i < n4; i += stride) {
        float4 v = ((const float4*)w)[i];
        float q0 = fminf(fmaxf(rintf(__fdiv_rn(v.x, s) + zp), 0.0f), 255.0f) - zp;
        float q1 = fminf(fmaxf(rintf(__fdiv_rn(v.y, s) + zp), 0.0f), 255.0f) - zp;
        float q2 = fminf(fmaxf(rintf(__fdiv_rn(v.z, s) + zp), 0.0f), 255.0f) - zp;
        float q3 = fminf(fmaxf(rintf(__fdiv_rn(v.w, s) + zp), 0.0f), 255.0f) - zp;
        __nv_bfloat162* o = (__nv_bfloat162*)g_wqc + i * 2;
        o[0] = __nv_bfloat162(__float2bfloat16(q0), __float2bfloat16(q1));
        o[1] = __nv_bfloat162(__float2bfloat16(q2), __float2bfloat16(q3));
    }
}

// split x into bf16 hi + lo
__global__ void xsplit_kernel(const float* __restrict__ x, long n4) {
    long stride = (long)gridDim.x * blockDim.x;
    for (long i = (long)blockIdx.x * blockDim.x + threadIdx.x; i < n4; i += stride) {
        float4 v = ((const float4*)x)[i];
        __nv_bfloat16 h0 = __float2bfloat16(v.x);
        __nv_bfloat16 h1 = __float2bfloat16(v.y);
        __nv_bfloat16 h2 = __float2bfloat16(v.z);
        __nv_bfloat16 h3 = __float2bfloat16(v.w);
        __nv_bfloat162* oh = (__nv_bfloat162*)g_xh + i * 2;
        oh[0] = __nv_bfloat162(h0, h1);
        oh[1] = __nv_bfloat162(h2, h3);
        __nv_bfloat162* ol = (__nv_bfloat162*)g_xl + i * 2;
        ol[0] = __nv_bfloat162(__float2bfloat16(v.x - __bfloat162float(h0)),
                               __float2bfloat16(v.y - __bfloat162float(h1)));
        ol[1] = __nv_bfloat162(__float2bfloat16(v.z - __bfloat162float(h2)),
                               __float2bfloat16(v.w - __bfloat162float(h3)));
    }
}

// ---------------------------------------------------------------------------
// bf16 2-pass GEMM: out = s*( (xh+xl) @ Qc^T ) + bias.
// CTA 128x128, BK=32 bf16 (64B rows), 4-stage cp.async ring, one sync/chunk.
// smem swizzle: chunk' = chunk ^ ((row>>1)&3) -> conflict-free ldmatrix mats.
// ---------------------------------------------------------------------------
__global__ __launch_bounds__(NTH, 2)
void gemm_bf16_kernel(const float* __restrict__ bias, float* __restrict__ out,
                      int IND, int ND, int nPerCluster) {
    extern __shared__ char smc[];
    const int tid = threadIdx.x;
    const int lane = tid & 31, wid = tid >> 5;
    const int q = lane & 3, r4 = lane >> 2;
    const int wm = wid & 3, wn = wid >> 2;   // 4x2 warp grid, warp 32x64
    const int Rw = wm * 32, Cw = wn * 64;
    const int m0 = blockIdx.y * BM;
    const int n0 = blockIdx.x * BN;
    const uint32_t sb = smem_u32(smc);

    float acc[2][8][4];
    #pragma unroll
    for (int mi = 0; mi < 2; mi++)
        #pragma unroll
        for (int nb = 0; nb < 8; nb++)
            #pragma unroll
            for (int e = 0; e < 4; e++) acc[mi][nb][e] = 0.0f;

    // cp.async issue: 512 16B chunks per tensor, 2 per thread per tensor
    auto issue = [&](int ck, int s) {
        const uint32_t st = sb + s * STG_B;
        const long kk = (long)ck * BKB;
        #pragma unroll
        for (int i = 0; i < 2; i++) {
            int c = tid + i * 256;
            int r = c >> 2, g = c & 3;
            uint32_t d = (uint32_t)(r * 64 + ((g ^ ((r >> 1) & 3)) << 4));
            long goff = kk + g * 8;
            cp16(st + d,          g_xh  + (size_t)(m0 + r) * IND + goff);
            cp16(st + OFF_AL + d, g_xl  + (size_t)(m0 + r) * IND + goff);
            cp16(st + OFF_B + d,  g_wqc + (size_t)(n0 + r) * IND + goff);
        }
    };

    // ldmatrix lane bases (identical to validated R8 kernel)
    const int arow_base = (lane & 7) + ((lane >> 3) & 1) * 8;
    const int ag = lane >> 4;
    const int brow_base = lane & 7;
    const int bg = lane >> 3;

    auto compute = [&](int s) {
        const uint32_t st = sb + s * STG_B;
        uint32_t ah[2][2][4], al[2][2][4];
        #pragma unroll
        for (int mi = 0; mi < 2; mi++)
            #pragma unroll
            for (int at = 0; at < 2; at++) {
                int r = Rw + mi * 16 + arow_base;
                int g = at * 2 + ag;
                uint32_t off = (uint32_t)(r * 64 + ((g ^ ((r >> 1) & 3)) << 4));
                ldsm4(ah[mi][at], st + off);
                ldsm4(al[mi][at], st + OFF_AL + off);
            }
        #pragma unroll
        for (int nb = 0; nb < 8; nb++) {
            int r = Cw + nb * 8 + brow_base;
            uint32_t off = (uint32_t)(r * 64 + ((bg ^ ((r >> 1) & 3)) << 4));
            uint32_t b[4];
            ldsm4(b, st + OFF_B + off);
            #pragma unroll
            for (int mi = 0; mi < 2; mi++) {
                float* d = acc[mi][nb];
                mma16(d, ah[mi][0], b[0], b[1]);
                mma16(d, al[mi][0], b[0], b[1]);
                mma16(d, ah[mi][1], b[2], b[3]);
                mma16(d, al[mi][1], b[2], b[3]);
            }
        }
    };

    const int NCH = IND / BKB;   // 128

    // prologue: NSTG-1 = 3 chunks in flight
    issue(0, 0); cp_commit();
    issue(1, 1); cp_commit();
    issue(2, 2); cp_commit();

    // mainloop: one __syncthreads per chunk.
    // iter k: wait until chunk k landed; sync (protects stage (k-1)%4, read
    // last iter, from this iter's issue of chunk k+3 -> stage (k+3)%4=(k-1)%4).
    for (int k = 0; k < NCH; k++) {
        cp_wait<2>();
        __syncthreads();
        if (k + 3 < NCH) issue(k + 3, (k + 3) & (NSTG - 1));
        cp_commit();   // commit every iter (possibly empty) to keep counts
        compute(k & (NSTG - 1));
    }

    // epilogue: scale by s, +bias, per-cluster min/max, direct stores
    const float sf = g_sw;
    float lmin = FLT_BIG, lmax = -FLT_BIG;
    float2 bz[8];
    #pragma unroll
    for (int nb = 0; nb < 8; nb++)
        bz[nb] = *(const float2*)(bias + n0 + Cw + nb * 8 + 2 * q);

    #pragma unroll
    for (int mi = 0; mi < 2; mi++) {
        int r0 = m0 + Rw + mi * 16 + r4;
        #pragma unroll
        for (int nb = 0; nb < 8; nb++) {
            int col = n0 + Cw + nb * 8 + 2 * q;
            float v0 = sf * acc[mi][nb][0] + bz[nb].x;
            float v1 = sf * acc[mi][nb][1] + bz[nb].y;
            float v2 = sf * acc[mi][nb][2] + bz[nb].x;
            float v3 = sf * acc[mi][nb][3] + bz[nb].y;
            lmin = fminf(lmin, fminf(fminf(v0, v1), fminf(v2, v3)));
            lmax = fmaxf(lmax, fmaxf(fmaxf(v0, v1), fmaxf(v2, v3)));
            *(float2*)(out + (size_t)r0 * ND + col)       = make_float2(v0, v1);
            *(float2*)(out + (size_t)(r0 + 8) * ND + col) = make_float2(v2, v3);
        }
    }

    #pragma unroll
    for (int o = 16; o; o >>= 1) {
        lmin = fminf(lmin, __shfl_down_sync(0xFFFFFFFFu, lmin, o));
        lmax = fmaxf(lmax, __shfl_down_sync(0xFFFFFFFFu, lmax, o));
    }
    __shared__ float smn[8], smx[8];
    if (!lane) { smn[wid] = lmin; smx[wid] = lmax; }
    __syncthreads();
    if (tid == 0) {
        float mn = smn[0], mx = smx[0];
        #pragma unroll
        for (int i = 1; i < 8; i++) { mn = fminf(mn, smn[i]); mx = fmaxf(mx, smx[i]); }
        int cl = m0 / nPerCluster;
        atomicMin(&g_cmin[cl], f2ord(mn));
        atomicMax(&g_cmax[cl], f2ord(mx));
    }
}

// ---------------------------------------------------------------------------
__global__ void range_kernel(const float* __restrict__ act_range,
                             const int* __restrict__ cinfo,
                             float* __restrict__ rout, int Kc) {
    int t = threadIdx.x;
    if (t < 2 * Kc) rout[t] = act_range[t];
    __syncthreads();
    if (t < Kc) {
        int c = cinfo[2 * t];
        float mn = ord2f(g_cmin[t]);
        float mx = ord2f(g_cmax[t]);
        float om = act_range[2 * c], oM = act_range[2 * c + 1];
        const float SM  = 0.999f;
        const float OMS = (float)(1.0 - 0.999);
        float nm = om * SM + mn * OMS;
        float nM = oM * SM + mx * OMS;
        rout[2 * c]     = nm;
        rout[2 * c + 1] = nM;
        float s = __fdiv_rn(nM - nm, 255.0f);
        g_s3[t] = s;
        g_z3[t] = -rintf(__fdiv_rn(nm, s));
    }
}

// ---------------------------------------------------------------------------
__global__ void quant_out_kernel(float* __restrict__ out, long total4,
                                 int ND, int nPerCluster) {
    long stride = (long)gridDim.x * blockDim.x;
    for (long i = (long)blockIdx.x * blockDim.x + threadIdx.x; i < total4; i += stride) {
        long e = i * 4;
        int row = (int)(e / ND);
        int g = row / nPerCluster;
        float s = g_s3[g], zp = g_z3[g];
        float4 v = ((float4*)out)[i];
        v.x = (fminf(fmaxf(rintf(__fdiv_rn(v.x, s) + zp), 0.0f), 255.0f) - zp) * s;
        v.y = (fminf(fmaxf(rintf(__fdiv_rn(v.y, s) + zp), 0.0f), 255.0f) - zp) * s;
        v.z = (fminf(fmaxf(rintf(__fdiv_rn(v.z, s) + zp), 0.0f), 255.0f) - zp) * s;
        v.w = (fminf(fmaxf(rintf(__fdiv_rn(v.w, s) + zp), 0.0f), 255.0f) - zp) * s;
        ((float4*)out)[i] = v;
    }
}

// ---------------------------------------------------------------------------
extern "C" void kernel_launch(void* const* d_in, const int* in_sizes, int n_in,
                              void* d_out, int out_size) {
    const float* x         = (const float*)d_in[0];
    const float* weight    = (const float*)d_in[1];
    const float* bias      = (const float*)d_in[2];
    const float* act_range = (const float*)d_in[3];
    const int*   cinfo     = (const int*)d_in[4];

    int OUT = in_sizes[2];             // bias length
    int IN  = in_sizes[1] / OUT;       // weight is [OUT, IN]
    int B   = in_sizes[0] / IN;        // x is [B, IN]
    int Kc  = in_sizes[3] / 2;         // act_range [K, 2]
    int nPer = B / Kc;

    float* out  = (float*)d_out;
    float* rout = out + (size_t)B * OUT;

    long w4 = (long)OUT * IN / 4;
    long x4 = (long)B * IN / 4;
    long o4 = (long)B * OUT / 4;

    init_scratch_kernel<<<1, 64>>>();
    wminmax_kernel<<<1024, 256>>>(weight, w4);
    wparams_kernel<<<1, 1>>>();
    wquant_kernel<<<2048, 256>>>(weight, w4);
    xsplit_kernel<<<4096, 256>>>(x, x4);

    cudaFuncSetAttribute(gemm_bf16_kernel,
                         cudaFuncAttributeMaxDynamicSharedMemorySize, SMEM_BYTES);
    dim3 grid(OUT / BN, B / BM);
    gemm_bf16_kernel<<<grid, NTH, SMEM_BYTES>>>(bias, out, IN, OUT, nPer);

    range_kernel<<<1, 128>>>(act_range, cinfo, rout, Kc);
    quant_out_kernel<<<2048, 256>>>(out, o4, OUT, nPer);
}